// round 6
// baseline (speedup 1.0000x reference)
#include <cuda_runtime.h>
#include <math.h>
#include <stdint.h>

// Problem constants
#define BB 2
#define SS 576
#define FF 16
#define DD 512
#define HH 8
#define CC 64
#define MROWS (BB*SS*FF)   // 18432
#define NSPLIT 8

// Scratch (allocation-free: __device__ globals)
__device__ float g_q[MROWS*DD];
__device__ float g_k[MROWS*DD];
__device__ float g_v[MROWS*DD];
__device__ float g_att[MROWS*DD];
__device__ float g_opart[NSPLIT*BB*HH*SS*CC];   // resq split partials (normalized)
__device__ float g_ml[NSPLIT*BB*HH*SS*2];       // per-row (m, l) per split
__device__ int   g_frames[BB][FF];
__device__ int   g_df[BB];

__device__ __forceinline__ float to_tf32(float x) {
    float r;
    asm("cvt.rna.tf32.f32 %0, %1;" : "=f"(r) : "f"(x));
    return r;
}

// m16n8k8 tf32 MMA, fp32 accumulate. (lane l, g=l/4, t=l%4):
//  A(16x8): a0=A[g][t] a1=A[g+8][t] a2=A[g][t+4] a3=A[g+8][t+4]
//  B(8x8):  b0=B[t][g] b1=B[t+4][g]
//  D(16x8): d0=D[g][2t] d1=D[g][2t+1] d2=D[g+8][2t] d3=D[g+8][2t+1]
__device__ __forceinline__ void mma_tf32(float d[4], const uint32_t a[4], const uint32_t b[2]) {
    asm("mma.sync.aligned.m16n8k8.row.col.f32.tf32.tf32.f32 "
        "{%0,%1,%2,%3}, {%4,%5,%6,%7}, {%8,%9}, {%0,%1,%2,%3};"
        : "+f"(d[0]), "+f"(d[1]), "+f"(d[2]), "+f"(d[3])
        : "r"(a[0]), "r"(a[1]), "r"(a[2]), "r"(a[3]),
          "r"(b[0]), "r"(b[1]));
}

// ---------------------------------------------------------------------------
__global__ void build_frames_kernel(const int* __restrict__ mask)
{
    if (threadIdx.x == 0 && blockIdx.x == 0) {
        for (int b = 0; b < BB; b++) {
            int n = 0;
            g_frames[b][n++] = 0;
            g_frames[b][n++] = 1;
            for (int f = 2; f < FF; f++)
                if (mask[b*(FF-2) + (f-2)] == 0) g_frames[b][n++] = f;
            g_df[b] = n;
        }
    }
}

// ---------------------------------------------------------------------------
// tf32 MMA GEMM, z-fused over up to 3 weight matrices sharing the same A.
// Block 128x128, KC=16, 256 threads (8 warps: 4m x 2n), warp tile 32x64.
// ---------------------------------------------------------------------------
__global__ __launch_bounds__(256) void gemm_tf32_kernel(
    const float* __restrict__ A,
    const float* __restrict__ W0, const float* __restrict__ W1, const float* __restrict__ W2,
    float* __restrict__ C0, float* __restrict__ C1, float* __restrict__ C2,
    const float* __restrict__ bias)
{
    __shared__ float As[128][20];    // [m][k], pad 4
    __shared__ float Bs[16][136];    // [k][n], pad 8

    const int z = blockIdx.z;
    const float* W = (z == 0) ? W0 : (z == 1) ? W1 : W2;
    float* C       = (z == 0) ? C0 : (z == 1) ? C1 : C2;

    const int tid = threadIdx.x;
    const int lid = tid & 31, wid = tid >> 5;
    const int gID = lid >> 2, ct = lid & 3;
    const int warpM = wid >> 1;
    const int warpN = wid & 1;
    const int bm = blockIdx.x * 128;
    const int bn = blockIdx.y * 128;

    const int a_row0 = tid >> 2,        a_c4 = tid & 3;
    const int a_row1 = (tid + 256) >> 2;
    const int b_k0   = tid >> 5,        b_n4 = tid & 31;
    const int b_k1   = (tid + 256) >> 5;

    const float* Ap0 = A + (size_t)(bm + a_row0) * DD + a_c4 * 4;
    const float* Ap1 = A + (size_t)(bm + a_row1) * DD + a_c4 * 4;
    const float* Bp0 = W + (size_t)b_k0 * DD + bn + b_n4 * 4;
    const float* Bp1 = W + (size_t)b_k1 * DD + bn + b_n4 * 4;

    float acc[2][8][4];
#pragma unroll
    for (int mf = 0; mf < 2; mf++)
#pragma unroll
        for (int nf = 0; nf < 8; nf++)
#pragma unroll
            for (int r = 0; r < 4; r++) acc[mf][nf][r] = 0.f;

    float4 ra0 = *(const float4*)(Ap0);
    float4 ra1 = *(const float4*)(Ap1);
    float4 rb0 = *(const float4*)(Bp0);
    float4 rb1 = *(const float4*)(Bp1);

    for (int k0 = 0; k0 < DD; k0 += 16) {
        __syncthreads();
        {
            float4 c0 = make_float4(to_tf32(ra0.x), to_tf32(ra0.y), to_tf32(ra0.z), to_tf32(ra0.w));
            float4 c1 = make_float4(to_tf32(ra1.x), to_tf32(ra1.y), to_tf32(ra1.z), to_tf32(ra1.w));
            float4 c2 = make_float4(to_tf32(rb0.x), to_tf32(rb0.y), to_tf32(rb0.z), to_tf32(rb0.w));
            float4 c3 = make_float4(to_tf32(rb1.x), to_tf32(rb1.y), to_tf32(rb1.z), to_tf32(rb1.w));
            *(float4*)&As[a_row0][a_c4*4] = c0;
            *(float4*)&As[a_row1][a_c4*4] = c1;
            *(float4*)&Bs[b_k0][b_n4*4]   = c2;
            *(float4*)&Bs[b_k1][b_n4*4]   = c3;
        }
        __syncthreads();

        if (k0 + 16 < DD) {
            ra0 = *(const float4*)(Ap0 + k0 + 16);
            ra1 = *(const float4*)(Ap1 + k0 + 16);
            rb0 = *(const float4*)(Bp0 + (size_t)(k0 + 16) * DD);
            rb1 = *(const float4*)(Bp1 + (size_t)(k0 + 16) * DD);
        }

#pragma unroll
        for (int kc = 0; kc < 16; kc += 8) {
            uint32_t afr[2][4];
#pragma unroll
            for (int mf = 0; mf < 2; mf++) {
                int m = warpM * 32 + mf * 16;
                afr[mf][0] = __float_as_uint(As[m + gID    ][kc + ct    ]);
                afr[mf][1] = __float_as_uint(As[m + gID + 8][kc + ct    ]);
                afr[mf][2] = __float_as_uint(As[m + gID    ][kc + ct + 4]);
                afr[mf][3] = __float_as_uint(As[m + gID + 8][kc + ct + 4]);
            }
#pragma unroll
            for (int nf = 0; nf < 8; nf++) {
                int n = warpN * 64 + nf * 8 + gID;
                uint32_t bfr[2];
                bfr[0] = __float_as_uint(Bs[kc + ct    ][n]);
                bfr[1] = __float_as_uint(Bs[kc + ct + 4][n]);
                mma_tf32(acc[0][nf], afr[0], bfr);
                mma_tf32(acc[1][nf], afr[1], bfr);
            }
        }
    }

#pragma unroll
    for (int mf = 0; mf < 2; mf++) {
        int r = bm + warpM * 32 + mf * 16 + gID;
#pragma unroll
        for (int nf = 0; nf < 8; nf++) {
            int cidx = bn + warpN * 64 + nf * 8 + ct * 2;
            float b0 = 0.f, b1 = 0.f;
            if (bias) { b0 = bias[cidx]; b1 = bias[cidx + 1]; }
            float2 v0 = make_float2(acc[mf][nf][0] + b0, acc[mf][nf][1] + b1);
            float2 v1 = make_float2(acc[mf][nf][2] + b0, acc[mf][nf][3] + b1);
            *(float2*)&C[(size_t)r * DD + cidx] = v0;
            *(float2*)&C[(size_t)(r + 8) * DD + cidx] = v1;
        }
    }
}

// ---------------------------------------------------------------------------
// Flash attention, tf32 MMA, pipelined.
// 64q tiles, 128 threads (4 warps, 16 q-rows each, full key range per warp).
// Ping-pong smem K/V buffers (dynamic); next-K prefetched during S, next-V
// during PV. P aliases the current K buffer. Q frags in regs (pre-scaled).
// MODE 0 (ress): direct output. MODE 1 (resq): split-KV over blockIdx.z,
// writes normalized partials + (m,l) for later merge.
// smem layout: Ks[2][64][68], Vs[2][64][72]  (71680 bytes)
// ---------------------------------------------------------------------------
#define KS_STRIDE 68
#define VS_STRIDE 72
#define KS_BUF (64*KS_STRIDE)
#define VS_BUF (64*VS_STRIDE)
#define SMEM_ATTN ((2*KS_BUF + 2*VS_BUF)*4)

template<int MODE>
__global__ __launch_bounds__(128) void attn_mma_kernel(
    const float* __restrict__ Qg, const float* __restrict__ Kg,
    const float* __restrict__ Vg, float* __restrict__ Og,
    float* __restrict__ Opart, float* __restrict__ Ml)
{
    extern __shared__ float sm[];
    float* Ksm = sm;                // [2][64][68]
    float* Vsm = sm + 2*KS_BUF;     // [2][64][72]

    const int tid = threadIdx.x;
    const int lid = tid & 31, w = tid >> 5;
    const int gID = lid >> 2, ct = lid & 3;
    const int q0 = blockIdx.x * 64;

    int b, h, f, qf, df = 1, t0, t1;
    if (MODE == 0) {
        int y = blockIdx.y;
        b = y / ((FF-1) * HH);
        int r = y % ((FF-1) * HH);
        f = 1 + r / HH;
        h = r % HH;
        qf = f;
        t0 = 0; t1 = SS / 64;
    } else {
        int y = blockIdx.y;
        b = y >> 3;
        h = y & 7;
        qf = 0; f = 0;
        df = g_df[b];
        int ntot = (SS / 64) * df;
        int sp = blockIdx.z;
        t0 = sp * ntot / NSPLIT;
        t1 = (sp + 1) * ntot / NSPLIT;
    }

    // Q fragments in registers (rows w*16+gID, +8), pre-scaled by 1/8
    uint32_t qa[8][4];
    {
        const int r0 = q0 + w * 16 + gID;
        const size_t base0 = ((size_t)(b*SS + r0    ) * FF + qf) * DD + h * CC;
        const size_t base1 = ((size_t)(b*SS + r0 + 8) * FF + qf) * DD + h * CC;
#pragma unroll
        for (int kc = 0; kc < 8; kc++) {
            qa[kc][0] = __float_as_uint(to_tf32(Qg[base0 + kc*8 + ct    ] * 0.125f));
            qa[kc][1] = __float_as_uint(to_tf32(Qg[base1 + kc*8 + ct    ] * 0.125f));
            qa[kc][2] = __float_as_uint(to_tf32(Qg[base0 + kc*8 + ct + 4] * 0.125f));
            qa[kc][3] = __float_as_uint(to_tf32(Qg[base1 + kc*8 + ct + 4] * 0.125f));
        }
    }

    float o[8][4];
#pragma unroll
    for (int nf = 0; nf < 8; nf++)
#pragma unroll
        for (int r = 0; r < 4; r++) o[nf][r] = 0.f;
    float m0 = -1e30f, m1 = -1e30f, l0 = 0.f, l1 = 0.f;

    // K/V tile load assignment: key = tid&63 (phase-friendly), half of c
    const int key   = tid & 63;
    const int chalf = (tid >> 6) * 32;

    // Global row base for a tile index kt (recomputed per use)
    auto row_of = [&](int kt) -> size_t {
        int kg = kt * 64 + key;
        int sk, fk;
        if (MODE == 0) { sk = kg; fk = f; }
        else           { sk = kg / df; fk = g_frames[b][kg - sk*df]; }
        return ((size_t)(b*SS + sk) * FF + fk) * DD + h * CC + chalf;
    };

    float4 kreg[8], vreg[8];
    {
        size_t r = row_of(t0);
#pragma unroll
        for (int u = 0; u < 8; u++) kreg[u] = *(const float4*)&Kg[r + u*4];
#pragma unroll
        for (int u = 0; u < 8; u++) vreg[u] = *(const float4*)&Vg[r + u*4];
    }

    const int pr0 = w * 16 + gID, pr1 = pr0 + 8;

    for (int kt = t0; kt < t1; kt++) {
        const int cur = kt & 1;
        float* Kb = Ksm + cur * KS_BUF;
        float* Vb = Vsm + cur * VS_BUF;

        // Store prefetched tile to smem (cvt to tf32, vectorized)
        {
            float* kd = Kb + key * KS_STRIDE + chalf;
            float* vd = Vb + key * VS_STRIDE + chalf;
#pragma unroll
            for (int u = 0; u < 8; u++) {
                float4 kc4 = make_float4(to_tf32(kreg[u].x), to_tf32(kreg[u].y),
                                         to_tf32(kreg[u].z), to_tf32(kreg[u].w));
                *(float4*)(kd + u*4) = kc4;
            }
#pragma unroll
            for (int u = 0; u < 8; u++) {
                float4 vc4 = make_float4(to_tf32(vreg[u].x), to_tf32(vreg[u].y),
                                         to_tf32(vreg[u].z), to_tf32(vreg[u].w));
                *(float4*)(vd + u*4) = vc4;
            }
        }
        __syncthreads();

        // Prefetch next K tile (latency hidden by S + softmax)
        if (kt + 1 < t1) {
            size_t r = row_of(kt + 1);
#pragma unroll
            for (int u = 0; u < 8; u++) kreg[u] = *(const float4*)&Kg[r + u*4];
        }

        // S = (Q*sc) K^T : A=Q rows, B=K^T (k=c, n=key); K stored [key][c]
        float s[8][4];
#pragma unroll
        for (int nf = 0; nf < 8; nf++)
#pragma unroll
            for (int r = 0; r < 4; r++) s[nf][r] = 0.f;
#pragma unroll
        for (int kc = 0; kc < 8; kc++) {
#pragma unroll
            for (int nf = 0; nf < 8; nf++) {
                uint32_t bfr[2];
                bfr[0] = __float_as_uint(Kb[(nf*8 + gID) * KS_STRIDE + kc*8 + ct    ]);
                bfr[1] = __float_as_uint(Kb[(nf*8 + gID) * KS_STRIDE + kc*8 + ct + 4]);
                mma_tf32(s[nf], qa[kc], bfr);
            }
        }

        // Online softmax (rows gID -> regs 0,1 and gID+8 -> regs 2,3)
        float mx0 = -1e30f, mx1 = -1e30f;
#pragma unroll
        for (int nf = 0; nf < 8; nf++) {
            mx0 = fmaxf(mx0, fmaxf(s[nf][0], s[nf][1]));
            mx1 = fmaxf(mx1, fmaxf(s[nf][2], s[nf][3]));
        }
        mx0 = fmaxf(mx0, __shfl_xor_sync(0xffffffffu, mx0, 1));
        mx0 = fmaxf(mx0, __shfl_xor_sync(0xffffffffu, mx0, 2));
        mx1 = fmaxf(mx1, __shfl_xor_sync(0xffffffffu, mx1, 1));
        mx1 = fmaxf(mx1, __shfl_xor_sync(0xffffffffu, mx1, 2));

        float m0n = fmaxf(m0, mx0), m1n = fmaxf(m1, mx1);
        float a0 = __expf(m0 - m0n), a1 = __expf(m1 - m1n);
        float s0 = 0.f, s1 = 0.f;
#pragma unroll
        for (int nf = 0; nf < 8; nf++) {
            s[nf][0] = __expf(s[nf][0] - m0n);
            s[nf][1] = __expf(s[nf][1] - m0n);
            s[nf][2] = __expf(s[nf][2] - m1n);
            s[nf][3] = __expf(s[nf][3] - m1n);
            s0 += s[nf][0] + s[nf][1];
            s1 += s[nf][2] + s[nf][3];
        }
        s0 += __shfl_xor_sync(0xffffffffu, s0, 1);
        s0 += __shfl_xor_sync(0xffffffffu, s0, 2);
        s1 += __shfl_xor_sync(0xffffffffu, s1, 1);
        s1 += __shfl_xor_sync(0xffffffffu, s1, 2);
        l0 = l0 * a0 + s0; m0 = m0n;
        l1 = l1 * a1 + s1; m1 = m1n;
#pragma unroll
        for (int nf = 0; nf < 8; nf++) {
            o[nf][0] *= a0; o[nf][1] *= a0;
            o[nf][2] *= a1; o[nf][3] *= a1;
        }

        __syncthreads();   // all warps done reading Kb as K

        // Store P (tf32) into Kb as [q][key]; own rows only
#pragma unroll
        for (int nf = 0; nf < 8; nf++) {
            int col = nf * 8 + ct * 2;
            *(float2*)&Kb[pr0 * KS_STRIDE + col] =
                make_float2(to_tf32(s[nf][0]), to_tf32(s[nf][1]));
            *(float2*)&Kb[pr1 * KS_STRIDE + col] =
                make_float2(to_tf32(s[nf][2]), to_tf32(s[nf][3]));
        }

        // Prefetch next V tile (latency hidden by PV)
        if (kt + 1 < t1) {
            size_t r = row_of(kt + 1);
#pragma unroll
            for (int u = 0; u < 8; u++) vreg[u] = *(const float4*)&Vg[r + u*4];
        }

        // O += P @ V : A=P rows, B=V (k=key, n=c); V stored [key][c]
#pragma unroll
        for (int kc = 0; kc < 8; kc++) {
            uint32_t pa[4];
            pa[0] = __float_as_uint(Kb[pr0 * KS_STRIDE + kc*8 + ct    ]);
            pa[1] = __float_as_uint(Kb[pr1 * KS_STRIDE + kc*8 + ct    ]);
            pa[2] = __float_as_uint(Kb[pr0 * KS_STRIDE + kc*8 + ct + 4]);
            pa[3] = __float_as_uint(Kb[pr1 * KS_STRIDE + kc*8 + ct + 4]);
#pragma unroll
            for (int nf = 0; nf < 8; nf++) {
                uint32_t bfr[2];
                bfr[0] = __float_as_uint(Vb[(kc*8 + ct    ) * VS_STRIDE + nf*8 + gID]);
                bfr[1] = __float_as_uint(Vb[(kc*8 + ct + 4) * VS_STRIDE + nf*8 + gID]);
                mma_tf32(o[nf], pa, bfr);
            }
        }
    }

    // Epilogue
    const float inv0 = 1.0f / l0, inv1 = 1.0f / l1;
    const int r0 = q0 + w * 16 + gID;
    if (MODE == 0) {
        const size_t ob0 = ((size_t)(b*SS + r0    ) * FF + f) * DD + h * CC;
        const size_t ob1 = ((size_t)(b*SS + r0 + 8) * FF + f) * DD + h * CC;
#pragma unroll
        for (int nf = 0; nf < 8; nf++) {
            int col = nf * 8 + ct * 2;
            *(float2*)&Og[ob0 + col] = make_float2(o[nf][0] * inv0, o[nf][1] * inv0);
            *(float2*)&Og[ob1 + col] = make_float2(o[nf][2] * inv1, o[nf][3] * inv1);
        }
    } else {
        const int y = blockIdx.y, sp = blockIdx.z;
        const size_t pb0 = ((size_t)(sp*(BB*HH) + y) * SS + r0    ) * CC;
        const size_t pb1 = ((size_t)(sp*(BB*HH) + y) * SS + r0 + 8) * CC;
#pragma unroll
        for (int nf = 0; nf < 8; nf++) {
            int col = nf * 8 + ct * 2;
            *(float2*)&Opart[pb0 + col] = make_float2(o[nf][0] * inv0, o[nf][1] * inv0);
            *(float2*)&Opart[pb1 + col] = make_float2(o[nf][2] * inv1, o[nf][3] * inv1);
        }
        if (ct == 0) {
            size_t mb = ((size_t)(sp*(BB*HH) + y) * SS + r0) * 2;
            Ml[mb + 0] = m0; Ml[mb + 1] = l0;
            Ml[mb + CC/4] = 0.f; // placeholder avoided; see below
        }
        if (ct == 0) {
            size_t mb1 = ((size_t)(sp*(BB*HH) + y) * SS + r0 + 8) * 2;
            Ml[mb1 + 0] = m1; Ml[mb1 + 1] = l1;
        }
    }
}

// ---------------------------------------------------------------------------
// Merge resq split partials into g_att frame 0.
// One thread per (y, q, c4): float4 over C.
// ---------------------------------------------------------------------------
__global__ __launch_bounds__(256) void merge_resq_kernel(float* __restrict__ att)
{
    int idx = blockIdx.x * 256 + threadIdx.x;           // over 16*576*16
    if (idx >= BB*HH*SS*(CC/4)) return;
    int c4 = idx & 15;
    int q  = (idx >> 4) % SS;
    int y  = idx / (16 * SS);

    float m[NSPLIT], l[NSPLIT];
    float mmax = -1e30f;
#pragma unroll
    for (int s = 0; s < NSPLIT; s++) {
        size_t mb = ((size_t)(s*(BB*HH) + y) * SS + q) * 2;
        m[s] = g_ml[mb]; l[s] = g_ml[mb + 1];
        mmax = fmaxf(mmax, m[s]);
    }
    float4 acc = make_float4(0.f, 0.f, 0.f, 0.f);
    float wsum = 0.f;
#pragma unroll
    for (int s = 0; s < NSPLIT; s++) {
        float wgt = __expf(m[s] - mmax) * l[s];
        const float4 ov = *(const float4*)&g_opart[(((size_t)(s*(BB*HH) + y) * SS + q) * CC) + c4*4];
        acc.x += wgt * ov.x; acc.y += wgt * ov.y;
        acc.z += wgt * ov.z; acc.w += wgt * ov.w;
        wsum += wgt;
    }
    float inv = 1.0f / wsum;
    int b = y >> 3, h = y & 7;
    float4 r = make_float4(acc.x*inv, acc.y*inv, acc.z*inv, acc.w*inv);
    *(float4*)&att[((size_t)(b*SS + q) * FF + 0) * DD + h*CC + c4*4] = r;
}

// ---------------------------------------------------------------------------
extern "C" void kernel_launch(void* const* d_in, const int* in_sizes, int n_in,
                              void* d_out, int out_size)
{
    const float* x    = (const float*)d_in[0];
    const int*   mask = (const int*)  d_in[1];
    const float* Wq   = (const float*)d_in[2];
    const float* Wk   = (const float*)d_in[3];
    const float* Wv   = (const float*)d_in[4];
    const float* Wout = (const float*)d_in[5];
    const float* bout = (const float*)d_in[6];
    float* out = (float*)d_out;

    float *q, *k, *v, *att, *opart, *ml;
    cudaGetSymbolAddress((void**)&q,     g_q);
    cudaGetSymbolAddress((void**)&k,     g_k);
    cudaGetSymbolAddress((void**)&v,     g_v);
    cudaGetSymbolAddress((void**)&att,   g_att);
    cudaGetSymbolAddress((void**)&opart, g_opart);
    cudaGetSymbolAddress((void**)&ml,    g_ml);

    static bool attr_set = false;
    if (!attr_set) {
        cudaFuncSetAttribute(attn_mma_kernel<0>,
            cudaFuncAttributeMaxDynamicSharedMemorySize, SMEM_ATTN);
        cudaFuncSetAttribute(attn_mma_kernel<1>,
            cudaFuncAttributeMaxDynamicSharedMemorySize, SMEM_ATTN);
        attr_set = true;
    }

    build_frames_kernel<<<1, 32>>>(mask);

    // Fused QKV projections (grid.z selects weight)
    gemm_tf32_kernel<<<dim3(MROWS/128, DD/128, 3), 256>>>(
        x, Wq, Wk, Wv, q, k, v, nullptr);

    // ress: per-frame self attention, frames 1..15
    attn_mma_kernel<0><<<dim3(SS/64, BB*(FF-1)*HH, 1), 128, SMEM_ATTN>>>(
        q, k, v, att, nullptr, nullptr);
    // resq: split-KV over NSPLIT
    attn_mma_kernel<1><<<dim3(SS/64, BB*HH, NSPLIT), 128, SMEM_ATTN>>>(
        q, k, v, att, opart, ml);
    merge_resq_kernel<<<(BB*HH*SS*(CC/4) + 255)/256, 256>>>(att);

    // Output projection + bias
    gemm_tf32_kernel<<<dim3(MROWS/128, DD/128, 1), 256>>>(
        att, Wout, Wout, Wout, out, out, out, bout);
}

// round 7
// speedup vs baseline: 1.0728x; 1.0728x over previous
#include <cuda_runtime.h>
#include <math.h>
#include <stdint.h>

// Problem constants
#define BB 2
#define SS 576
#define FF 16
#define DD 512
#define HH 8
#define CC 64
#define MROWS (BB*SS*FF)   // 18432
#define NSPLIT 8

// Scratch (allocation-free: __device__ globals)
__device__ float g_q[MROWS*DD];
__device__ float g_k[MROWS*DD];
__device__ float g_v[MROWS*DD];
__device__ float g_att[MROWS*DD];
__device__ float g_opart[NSPLIT*BB*HH*SS*CC];   // resq split partials (normalized)
__device__ float g_ml[NSPLIT*BB*HH*SS*2];       // per-row (m, l) per split
__device__ int   g_frames[BB][FF];
__device__ int   g_df[BB];

__device__ __forceinline__ float to_tf32(float x) {
    float r;
    asm("cvt.rna.tf32.f32 %0, %1;" : "=f"(r) : "f"(x));
    return r;
}

// m16n8k8 tf32 MMA, fp32 accumulate. (lane l, g=l/4, t=l%4):
//  A(16x8): a0=A[g][t] a1=A[g+8][t] a2=A[g][t+4] a3=A[g+8][t+4]
//  B(8x8):  b0=B[t][g] b1=B[t+4][g]
//  D(16x8): d0=D[g][2t] d1=D[g][2t+1] d2=D[g+8][2t] d3=D[g+8][2t+1]
__device__ __forceinline__ void mma_tf32(float d[4], const uint32_t a[4], const uint32_t b[2]) {
    asm("mma.sync.aligned.m16n8k8.row.col.f32.tf32.tf32.f32 "
        "{%0,%1,%2,%3}, {%4,%5,%6,%7}, {%8,%9}, {%0,%1,%2,%3};"
        : "+f"(d[0]), "+f"(d[1]), "+f"(d[2]), "+f"(d[3])
        : "r"(a[0]), "r"(a[1]), "r"(a[2]), "r"(a[3]),
          "r"(b[0]), "r"(b[1]));
}

__device__ __forceinline__ void cp_async16(float* smem_dst, const float* gsrc) {
    uint32_t s = (uint32_t)__cvta_generic_to_shared(smem_dst);
    asm volatile("cp.async.ca.shared.global [%0], [%1], 16;" :: "r"(s), "l"(gsrc));
}
#define CP_COMMIT() asm volatile("cp.async.commit_group;" ::: "memory")
#define CP_WAIT1()  asm volatile("cp.async.wait_group 1;" ::: "memory")
#define CP_WAIT0()  asm volatile("cp.async.wait_group 0;" ::: "memory")

// ---------------------------------------------------------------------------
__global__ void build_frames_kernel(const int* __restrict__ mask)
{
    if (threadIdx.x == 0 && blockIdx.x == 0) {
        for (int b = 0; b < BB; b++) {
            int n = 0;
            g_frames[b][n++] = 0;
            g_frames[b][n++] = 1;
            for (int f = 2; f < FF; f++)
                if (mask[b*(FF-2) + (f-2)] == 0) g_frames[b][n++] = f;
            g_df[b] = n;
        }
    }
}

// ---------------------------------------------------------------------------
// tf32 MMA GEMM, z-fused over up to 3 weight matrices sharing the same A.
// Block 128x128, KC=16, 256 threads (8 warps: 4m x 2n), warp tile 32x64.
// do_round != 0: outputs stored pre-rounded to tf32 (RNA) — consumers then
// skip their own cvt; numerics identical to cvt-at-consumer.
// ---------------------------------------------------------------------------
__global__ __launch_bounds__(256) void gemm_tf32_kernel(
    const float* __restrict__ A,
    const float* __restrict__ W0, const float* __restrict__ W1, const float* __restrict__ W2,
    float* __restrict__ C0, float* __restrict__ C1, float* __restrict__ C2,
    const float* __restrict__ bias, int do_round)
{
    __shared__ float As[128][20];    // [m][k], pad 4
    __shared__ float Bs[16][136];    // [k][n], pad 8

    const int z = blockIdx.z;
    const float* W = (z == 0) ? W0 : (z == 1) ? W1 : W2;
    float* C       = (z == 0) ? C0 : (z == 1) ? C1 : C2;

    const int tid = threadIdx.x;
    const int lid = tid & 31, wid = tid >> 5;
    const int gID = lid >> 2, ct = lid & 3;
    const int warpM = wid >> 1;
    const int warpN = wid & 1;
    const int bm = blockIdx.x * 128;
    const int bn = blockIdx.y * 128;

    const int a_row0 = tid >> 2,        a_c4 = tid & 3;
    const int a_row1 = (tid + 256) >> 2;
    const int b_k0   = tid >> 5,        b_n4 = tid & 31;
    const int b_k1   = (tid + 256) >> 5;

    const float* Ap0 = A + (size_t)(bm + a_row0) * DD + a_c4 * 4;
    const float* Ap1 = A + (size_t)(bm + a_row1) * DD + a_c4 * 4;
    const float* Bp0 = W + (size_t)b_k0 * DD + bn + b_n4 * 4;
    const float* Bp1 = W + (size_t)b_k1 * DD + bn + b_n4 * 4;

    float acc[2][8][4];
#pragma unroll
    for (int mf = 0; mf < 2; mf++)
#pragma unroll
        for (int nf = 0; nf < 8; nf++)
#pragma unroll
            for (int r = 0; r < 4; r++) acc[mf][nf][r] = 0.f;

    float4 ra0 = *(const float4*)(Ap0);
    float4 ra1 = *(const float4*)(Ap1);
    float4 rb0 = *(const float4*)(Bp0);
    float4 rb1 = *(const float4*)(Bp1);

    for (int k0 = 0; k0 < DD; k0 += 16) {
        __syncthreads();
        {
            float4 c0 = make_float4(to_tf32(ra0.x), to_tf32(ra0.y), to_tf32(ra0.z), to_tf32(ra0.w));
            float4 c1 = make_float4(to_tf32(ra1.x), to_tf32(ra1.y), to_tf32(ra1.z), to_tf32(ra1.w));
            float4 c2 = make_float4(to_tf32(rb0.x), to_tf32(rb0.y), to_tf32(rb0.z), to_tf32(rb0.w));
            float4 c3 = make_float4(to_tf32(rb1.x), to_tf32(rb1.y), to_tf32(rb1.z), to_tf32(rb1.w));
            *(float4*)&As[a_row0][a_c4*4] = c0;
            *(float4*)&As[a_row1][a_c4*4] = c1;
            *(float4*)&Bs[b_k0][b_n4*4]   = c2;
            *(float4*)&Bs[b_k1][b_n4*4]   = c3;
        }
        __syncthreads();

        if (k0 + 16 < DD) {
            ra0 = *(const float4*)(Ap0 + k0 + 16);
            ra1 = *(const float4*)(Ap1 + k0 + 16);
            rb0 = *(const float4*)(Bp0 + (size_t)(k0 + 16) * DD);
            rb1 = *(const float4*)(Bp1 + (size_t)(k0 + 16) * DD);
        }

#pragma unroll
        for (int kc = 0; kc < 16; kc += 8) {
            uint32_t afr[2][4];
#pragma unroll
            for (int mf = 0; mf < 2; mf++) {
                int m = warpM * 32 + mf * 16;
                afr[mf][0] = __float_as_uint(As[m + gID    ][kc + ct    ]);
                afr[mf][1] = __float_as_uint(As[m + gID + 8][kc + ct    ]);
                afr[mf][2] = __float_as_uint(As[m + gID    ][kc + ct + 4]);
                afr[mf][3] = __float_as_uint(As[m + gID + 8][kc + ct + 4]);
            }
#pragma unroll
            for (int nf = 0; nf < 8; nf++) {
                int n = warpN * 64 + nf * 8 + gID;
                uint32_t bfr[2];
                bfr[0] = __float_as_uint(Bs[kc + ct    ][n]);
                bfr[1] = __float_as_uint(Bs[kc + ct + 4][n]);
                mma_tf32(acc[0][nf], afr[0], bfr);
                mma_tf32(acc[1][nf], afr[1], bfr);
            }
        }
    }

#pragma unroll
    for (int mf = 0; mf < 2; mf++) {
        int r = bm + warpM * 32 + mf * 16 + gID;
#pragma unroll
        for (int nf = 0; nf < 8; nf++) {
            int cidx = bn + warpN * 64 + nf * 8 + ct * 2;
            float b0 = 0.f, b1 = 0.f;
            if (bias) { b0 = bias[cidx]; b1 = bias[cidx + 1]; }
            float2 v0 = make_float2(acc[mf][nf][0] + b0, acc[mf][nf][1] + b1);
            float2 v1 = make_float2(acc[mf][nf][2] + b0, acc[mf][nf][3] + b1);
            if (do_round) {
                v0.x = to_tf32(v0.x); v0.y = to_tf32(v0.y);
                v1.x = to_tf32(v1.x); v1.y = to_tf32(v1.y);
            }
            *(float2*)&C[(size_t)r * DD + cidx] = v0;
            *(float2*)&C[(size_t)(r + 8) * DD + cidx] = v1;
        }
    }
}

// ---------------------------------------------------------------------------
// Flash attention, tf32 MMA, cp.async pipelined.
// 64q tiles, 128 threads (4 warps, 16 q-rows each, full key range per warp).
// K/V arrive pre-rounded to tf32 (GEMM epilogue) -> cp.async straight to
// ping-pong smem, no register staging, no cvt in the hot loop.
// P never touches smem: S D-fragments are permuted to PV A-fragments with
// intra-quad shuffles. 2 barriers per tile.
// MODE 0 (ress): direct output. MODE 1 (resq): split-KV over blockIdx.z.
// ---------------------------------------------------------------------------
#define KS_STRIDE 68
#define VS_STRIDE 72
#define KS_BUF (64*KS_STRIDE)
#define VS_BUF (64*VS_STRIDE)
#define SMEM_ATTN ((2*KS_BUF + 2*VS_BUF)*4)

template<int MODE>
__global__ __launch_bounds__(128, 3) void attn_mma_kernel(
    const float* __restrict__ Qg, const float* __restrict__ Kg,
    const float* __restrict__ Vg, float* __restrict__ Og,
    float* __restrict__ Opart, float* __restrict__ Ml)
{
    extern __shared__ float sm[];
    float* Ksm = sm;                // [2][64][KS_STRIDE]
    float* Vsm = sm + 2*KS_BUF;     // [2][64][VS_STRIDE]

    const int tid = threadIdx.x;
    const int lid = tid & 31, w = tid >> 5;
    const int gID = lid >> 2, ct = lid & 3;
    const int q0 = blockIdx.x * 64;

    int b, h, f, qf, df = 1, t0, t1;
    if (MODE == 0) {
        int y = blockIdx.y;
        b = y / ((FF-1) * HH);
        int r = y % ((FF-1) * HH);
        f = 1 + r / HH;
        h = r % HH;
        qf = f;
        t0 = 0; t1 = SS / 64;
    } else {
        int y = blockIdx.y;
        b = y >> 3;
        h = y & 7;
        qf = 0; f = 0;
        df = g_df[b];
        int ntot = (SS / 64) * df;
        int sp = blockIdx.z;
        t0 = sp * ntot / NSPLIT;
        t1 = (sp + 1) * ntot / NSPLIT;
    }

    // Q fragments (already tf32-rounded in gmem); scale by 1/8 (exact pow2)
    uint32_t qa[8][4];
    {
        const int r0 = q0 + w * 16 + gID;
        const size_t base0 = ((size_t)(b*SS + r0    ) * FF + qf) * DD + h * CC;
        const size_t base1 = ((size_t)(b*SS + r0 + 8) * FF + qf) * DD + h * CC;
#pragma unroll
        for (int kc = 0; kc < 8; kc++) {
            qa[kc][0] = __float_as_uint(Qg[base0 + kc*8 + ct    ] * 0.125f);
            qa[kc][1] = __float_as_uint(Qg[base1 + kc*8 + ct    ] * 0.125f);
            qa[kc][2] = __float_as_uint(Qg[base0 + kc*8 + ct + 4] * 0.125f);
            qa[kc][3] = __float_as_uint(Qg[base1 + kc*8 + ct + 4] * 0.125f);
        }
    }

    float o[8][4];
#pragma unroll
    for (int nf = 0; nf < 8; nf++)
#pragma unroll
        for (int r = 0; r < 4; r++) o[nf][r] = 0.f;
    float m0 = -1e30f, m1 = -1e30f, l0 = 0.f, l1 = 0.f;

    // K/V tile load assignment: one key row per pair of threads, 32 c each
    const int key   = tid & 63;
    const int chalf = (tid >> 6) * 32;

    auto row_of = [&](int kt) -> size_t {
        int kg = kt * 64 + key;
        int sk, fk;
        if (MODE == 0) { sk = kg; fk = f; }
        else           { sk = kg / df; fk = g_frames[b][kg - sk*df]; }
        return ((size_t)(b*SS + sk) * FF + fk) * DD + h * CC + chalf;
    };

    auto issue_tile = [&](int kt) {
        size_t r = row_of(kt);
        float* kd = Ksm + (kt & 1) * KS_BUF + key * KS_STRIDE + chalf;
        float* vd = Vsm + (kt & 1) * VS_BUF + key * VS_STRIDE + chalf;
#pragma unroll
        for (int u = 0; u < 8; u++) cp_async16(kd + u*4, Kg + r + u*4);
#pragma unroll
        for (int u = 0; u < 8; u++) cp_async16(vd + u*4, Vg + r + u*4);
    };

    issue_tile(t0);
    CP_COMMIT();

    // Shuffle-permute constants: S D-frag (cols 2t,2t+1) -> PV A-frag (cols t, t+4)
    const int srcA = (lid & ~3) | (ct >> 1);
    const int srcB = srcA + 2;
    const bool hi = (ct & 1);

    for (int kt = t0; kt < t1; kt++) {
        float* Kb = Ksm + (kt & 1) * KS_BUF;
        float* Vb = Vsm + (kt & 1) * VS_BUF;

        if (kt + 1 < t1) {
            issue_tile(kt + 1);
            CP_COMMIT();
            CP_WAIT1();
        } else {
            CP_WAIT0();
        }
        __syncthreads();   // all threads' cp.async for tile kt complete

        // S = (Q*sc) K^T : A=Q regs, B=K^T (k=c, n=key); K stored [key][c]
        float s[8][4];
#pragma unroll
        for (int nf = 0; nf < 8; nf++)
#pragma unroll
            for (int r = 0; r < 4; r++) s[nf][r] = 0.f;
#pragma unroll
        for (int kc = 0; kc < 8; kc++) {
#pragma unroll
            for (int nf = 0; nf < 8; nf++) {
                uint32_t bfr[2];
                bfr[0] = __float_as_uint(Kb[(nf*8 + gID) * KS_STRIDE + kc*8 + ct    ]);
                bfr[1] = __float_as_uint(Kb[(nf*8 + gID) * KS_STRIDE + kc*8 + ct + 4]);
                mma_tf32(s[nf], qa[kc], bfr);
            }
        }

        // Online softmax (rows gID -> regs 0,1 and gID+8 -> regs 2,3)
        float mx0 = -1e30f, mx1 = -1e30f;
#pragma unroll
        for (int nf = 0; nf < 8; nf++) {
            mx0 = fmaxf(mx0, fmaxf(s[nf][0], s[nf][1]));
            mx1 = fmaxf(mx1, fmaxf(s[nf][2], s[nf][3]));
        }
        mx0 = fmaxf(mx0, __shfl_xor_sync(0xffffffffu, mx0, 1));
        mx0 = fmaxf(mx0, __shfl_xor_sync(0xffffffffu, mx0, 2));
        mx1 = fmaxf(mx1, __shfl_xor_sync(0xffffffffu, mx1, 1));
        mx1 = fmaxf(mx1, __shfl_xor_sync(0xffffffffu, mx1, 2));

        float m0n = fmaxf(m0, mx0), m1n = fmaxf(m1, mx1);
        float a0 = __expf(m0 - m0n), a1 = __expf(m1 - m1n);
        float s0 = 0.f, s1 = 0.f;
#pragma unroll
        for (int nf = 0; nf < 8; nf++) {
            s[nf][0] = __expf(s[nf][0] - m0n);
            s[nf][1] = __expf(s[nf][1] - m0n);
            s[nf][2] = __expf(s[nf][2] - m1n);
            s[nf][3] = __expf(s[nf][3] - m1n);
            s0 += s[nf][0] + s[nf][1];
            s1 += s[nf][2] + s[nf][3];
        }
        s0 += __shfl_xor_sync(0xffffffffu, s0, 1);
        s0 += __shfl_xor_sync(0xffffffffu, s0, 2);
        s1 += __shfl_xor_sync(0xffffffffu, s1, 1);
        s1 += __shfl_xor_sync(0xffffffffu, s1, 2);
        l0 = l0 * a0 + s0; m0 = m0n;
        l1 = l1 * a1 + s1; m1 = m1n;
#pragma unroll
        for (int nf = 0; nf < 8; nf++) {
            o[nf][0] *= a0; o[nf][1] *= a0;
            o[nf][2] *= a1; o[nf][3] *= a1;
        }

        // O += P @ V : P A-frags built via intra-quad shuffles (no smem).
        // Key chunk kc2 == S column group kc2.
#pragma unroll
        for (int kc2 = 0; kc2 < 8; kc2++) {
            float p0 = s[kc2][0], p1 = s[kc2][1], p2 = s[kc2][2], p3 = s[kc2][3];
            float a0v0 = __shfl_sync(0xffffffffu, p0, srcA);
            float a0v1 = __shfl_sync(0xffffffffu, p1, srcA);
            float a1v0 = __shfl_sync(0xffffffffu, p2, srcA);
            float a1v1 = __shfl_sync(0xffffffffu, p3, srcA);
            float a2v0 = __shfl_sync(0xffffffffu, p0, srcB);
            float a2v1 = __shfl_sync(0xffffffffu, p1, srcB);
            float a3v0 = __shfl_sync(0xffffffffu, p2, srcB);
            float a3v1 = __shfl_sync(0xffffffffu, p3, srcB);
            uint32_t pa[4];
            pa[0] = __float_as_uint(to_tf32(hi ? a0v1 : a0v0));
            pa[1] = __float_as_uint(to_tf32(hi ? a1v1 : a1v0));
            pa[2] = __float_as_uint(to_tf32(hi ? a2v1 : a2v0));
            pa[3] = __float_as_uint(to_tf32(hi ? a3v1 : a3v0));
#pragma unroll
            for (int nf = 0; nf < 8; nf++) {
                uint32_t bfr[2];
                bfr[0] = __float_as_uint(Vb[(kc2*8 + ct    ) * VS_STRIDE + nf*8 + gID]);
                bfr[1] = __float_as_uint(Vb[(kc2*8 + ct + 4) * VS_STRIDE + nf*8 + gID]);
                mma_tf32(o[nf], pa, bfr);
            }
        }

        __syncthreads();   // everyone done with tile kt before next issue overwrites
    }

    // Epilogue
    const float inv0 = 1.0f / l0, inv1 = 1.0f / l1;
    const int r0 = q0 + w * 16 + gID;
    if (MODE == 0) {
        const size_t ob0 = ((size_t)(b*SS + r0    ) * FF + f) * DD + h * CC;
        const size_t ob1 = ((size_t)(b*SS + r0 + 8) * FF + f) * DD + h * CC;
#pragma unroll
        for (int nf = 0; nf < 8; nf++) {
            int col = nf * 8 + ct * 2;
            *(float2*)&Og[ob0 + col] = make_float2(o[nf][0] * inv0, o[nf][1] * inv0);
            *(float2*)&Og[ob1 + col] = make_float2(o[nf][2] * inv1, o[nf][3] * inv1);
        }
    } else {
        const int y = blockIdx.y, sp = blockIdx.z;
        const size_t pb0 = ((size_t)(sp*(BB*HH) + y) * SS + r0    ) * CC;
        const size_t pb1 = ((size_t)(sp*(BB*HH) + y) * SS + r0 + 8) * CC;
#pragma unroll
        for (int nf = 0; nf < 8; nf++) {
            int col = nf * 8 + ct * 2;
            *(float2*)&Opart[pb0 + col] = make_float2(o[nf][0] * inv0, o[nf][1] * inv0);
            *(float2*)&Opart[pb1 + col] = make_float2(o[nf][2] * inv1, o[nf][3] * inv1);
        }
        if (ct == 0) {
            size_t mb0 = ((size_t)(sp*(BB*HH) + y) * SS + r0) * 2;
            Ml[mb0 + 0] = m0; Ml[mb0 + 1] = l0;
            size_t mb1 = ((size_t)(sp*(BB*HH) + y) * SS + r0 + 8) * 2;
            Ml[mb1 + 0] = m1; Ml[mb1 + 1] = l1;
        }
    }
}

// ---------------------------------------------------------------------------
// Merge resq split partials into g_att frame 0.
// ---------------------------------------------------------------------------
__global__ __launch_bounds__(256) void merge_resq_kernel(float* __restrict__ att)
{
    int idx = blockIdx.x * 256 + threadIdx.x;           // over 16*576*16
    if (idx >= BB*HH*SS*(CC/4)) return;
    int c4 = idx & 15;
    int q  = (idx >> 4) % SS;
    int y  = idx / (16 * SS);

    float m[NSPLIT], l[NSPLIT];
    float mmax = -1e30f;
#pragma unroll
    for (int s = 0; s < NSPLIT; s++) {
        size_t mb = ((size_t)(s*(BB*HH) + y) * SS + q) * 2;
        m[s] = g_ml[mb]; l[s] = g_ml[mb + 1];
        mmax = fmaxf(mmax, m[s]);
    }
    float4 acc = make_float4(0.f, 0.f, 0.f, 0.f);
    float wsum = 0.f;
#pragma unroll
    for (int s = 0; s < NSPLIT; s++) {
        float wgt = __expf(m[s] - mmax) * l[s];
        const float4 ov = *(const float4*)&g_opart[(((size_t)(s*(BB*HH) + y) * SS + q) * CC) + c4*4];
        acc.x += wgt * ov.x; acc.y += wgt * ov.y;
        acc.z += wgt * ov.z; acc.w += wgt * ov.w;
        wsum += wgt;
    }
    float inv = 1.0f / wsum;
    int b = y >> 3, h = y & 7;
    float4 r = make_float4(acc.x*inv, acc.y*inv, acc.z*inv, acc.w*inv);
    *(float4*)&att[((size_t)(b*SS + q) * FF + 0) * DD + h*CC + c4*4] = r;
}

// ---------------------------------------------------------------------------
extern "C" void kernel_launch(void* const* d_in, const int* in_sizes, int n_in,
                              void* d_out, int out_size)
{
    const float* x    = (const float*)d_in[0];
    const int*   mask = (const int*)  d_in[1];
    const float* Wq   = (const float*)d_in[2];
    const float* Wk   = (const float*)d_in[3];
    const float* Wv   = (const float*)d_in[4];
    const float* Wout = (const float*)d_in[5];
    const float* bout = (const float*)d_in[6];
    float* out = (float*)d_out;

    float *q, *k, *v, *att, *opart, *ml;
    cudaGetSymbolAddress((void**)&q,     g_q);
    cudaGetSymbolAddress((void**)&k,     g_k);
    cudaGetSymbolAddress((void**)&v,     g_v);
    cudaGetSymbolAddress((void**)&att,   g_att);
    cudaGetSymbolAddress((void**)&opart, g_opart);
    cudaGetSymbolAddress((void**)&ml,    g_ml);

    static bool attr_set = false;
    if (!attr_set) {
        cudaFuncSetAttribute(attn_mma_kernel<0>,
            cudaFuncAttributeMaxDynamicSharedMemorySize, SMEM_ATTN);
        cudaFuncSetAttribute(attn_mma_kernel<1>,
            cudaFuncAttributeMaxDynamicSharedMemorySize, SMEM_ATTN);
        attr_set = true;
    }

    build_frames_kernel<<<1, 32>>>(mask);

    // Fused QKV projections; outputs pre-rounded to tf32 for the attention
    gemm_tf32_kernel<<<dim3(MROWS/128, DD/128, 3), 256>>>(
        x, Wq, Wk, Wv, q, k, v, nullptr, 1);

    // ress: per-frame self attention, frames 1..15
    attn_mma_kernel<0><<<dim3(SS/64, BB*(FF-1)*HH, 1), 128, SMEM_ATTN>>>(
        q, k, v, att, nullptr, nullptr);
    // resq: split-KV over NSPLIT
    attn_mma_kernel<1><<<dim3(SS/64, BB*HH, NSPLIT), 128, SMEM_ATTN>>>(
        q, k, v, att, opart, ml);
    merge_resq_kernel<<<(BB*HH*SS*(CC/4) + 255)/256, 256>>>(att);

    // Output projection + bias (final output: NOT rounded)
    gemm_tf32_kernel<<<dim3(MROWS/128, DD/128, 1), 256>>>(
        att, Wout, Wout, Wout, out, out, out, bout, 0);
}

// round 8
// speedup vs baseline: 1.2911x; 1.2036x over previous
#include <cuda_runtime.h>
#include <math.h>
#include <stdint.h>

// Problem constants
#define BB 2
#define SS 576
#define FF 16
#define DD 512
#define HH 8
#define CC 64
#define MROWS (BB*SS*FF)   // 18432
#define NSPLIT 8

// Scratch (allocation-free: __device__ globals)
__device__ float g_q[MROWS*DD];
__device__ float g_k[MROWS*DD];
__device__ float g_v[MROWS*DD];
__device__ float g_att[MROWS*DD];
__device__ float g_opart[NSPLIT*BB*HH*SS*CC];   // resq split partials (normalized)
__device__ float g_ml[NSPLIT*BB*HH*SS*2];       // per-row (m, l) per split
__device__ int   g_frames[BB][FF];
__device__ int   g_df[BB];

__device__ __forceinline__ float to_tf32(float x) {
    float r;
    asm("cvt.rna.tf32.f32 %0, %1;" : "=f"(r) : "f"(x));
    return r;
}

// m16n8k8 tf32 MMA, fp32 accumulate. (lane l, g=l/4, t=l%4):
//  A(16x8): a0=A[g][t] a1=A[g+8][t] a2=A[g][t+4] a3=A[g+8][t+4]
//  B(8x8):  b0=B[t][g] b1=B[t+4][g]
//  D(16x8): d0=D[g][2t] d1=D[g][2t+1] d2=D[g+8][2t] d3=D[g+8][2t+1]
__device__ __forceinline__ void mma_tf32(float d[4], const uint32_t a[4], const uint32_t b[2]) {
    asm("mma.sync.aligned.m16n8k8.row.col.f32.tf32.tf32.f32 "
        "{%0,%1,%2,%3}, {%4,%5,%6,%7}, {%8,%9}, {%0,%1,%2,%3};"
        : "+f"(d[0]), "+f"(d[1]), "+f"(d[2]), "+f"(d[3])
        : "r"(a[0]), "r"(a[1]), "r"(a[2]), "r"(a[3]),
          "r"(b[0]), "r"(b[1]));
}

__device__ __forceinline__ void cp_async16(float* smem_dst, const float* gsrc) {
    uint32_t s = (uint32_t)__cvta_generic_to_shared(smem_dst);
    asm volatile("cp.async.ca.shared.global [%0], [%1], 16;" :: "r"(s), "l"(gsrc));
}
#define CP_COMMIT() asm volatile("cp.async.commit_group;" ::: "memory")
#define CP_WAIT1()  asm volatile("cp.async.wait_group 1;" ::: "memory")
#define CP_WAIT0()  asm volatile("cp.async.wait_group 0;" ::: "memory")

// ---------------------------------------------------------------------------
__global__ void build_frames_kernel(const int* __restrict__ mask)
{
    if (threadIdx.x == 0 && blockIdx.x == 0) {
        for (int b = 0; b < BB; b++) {
            int n = 0;
            g_frames[b][n++] = 0;
            g_frames[b][n++] = 1;
            for (int f = 2; f < FF; f++)
                if (mask[b*(FF-2) + (f-2)] == 0) g_frames[b][n++] = f;
            g_df[b] = n;
        }
    }
}

// ---------------------------------------------------------------------------
// tf32 MMA GEMM, z-fused over up to 3 weight matrices sharing the same A.
// Block 128x128, KC=16, 256 threads (8 warps: 4m x 2n), warp tile 32x64.
// do_round != 0: outputs stored pre-rounded to tf32 (RNA).
// ---------------------------------------------------------------------------
__global__ __launch_bounds__(256) void gemm_tf32_kernel(
    const float* __restrict__ A,
    const float* __restrict__ W0, const float* __restrict__ W1, const float* __restrict__ W2,
    float* __restrict__ C0, float* __restrict__ C1, float* __restrict__ C2,
    const float* __restrict__ bias, int do_round)
{
    __shared__ float As[128][20];    // [m][k], pad 4
    __shared__ float Bs[16][136];    // [k][n], pad 8

    const int z = blockIdx.z;
    const float* W = (z == 0) ? W0 : (z == 1) ? W1 : W2;
    float* C       = (z == 0) ? C0 : (z == 1) ? C1 : C2;

    const int tid = threadIdx.x;
    const int lid = tid & 31, wid = tid >> 5;
    const int gID = lid >> 2, ct = lid & 3;
    const int warpM = wid >> 1;
    const int warpN = wid & 1;
    const int bm = blockIdx.x * 128;
    const int bn = blockIdx.y * 128;

    const int a_row0 = tid >> 2,        a_c4 = tid & 3;
    const int a_row1 = (tid + 256) >> 2;
    const int b_k0   = tid >> 5,        b_n4 = tid & 31;
    const int b_k1   = (tid + 256) >> 5;

    const float* Ap0 = A + (size_t)(bm + a_row0) * DD + a_c4 * 4;
    const float* Ap1 = A + (size_t)(bm + a_row1) * DD + a_c4 * 4;
    const float* Bp0 = W + (size_t)b_k0 * DD + bn + b_n4 * 4;
    const float* Bp1 = W + (size_t)b_k1 * DD + bn + b_n4 * 4;

    float acc[2][8][4];
#pragma unroll
    for (int mf = 0; mf < 2; mf++)
#pragma unroll
        for (int nf = 0; nf < 8; nf++)
#pragma unroll
            for (int r = 0; r < 4; r++) acc[mf][nf][r] = 0.f;

    float4 ra0 = *(const float4*)(Ap0);
    float4 ra1 = *(const float4*)(Ap1);
    float4 rb0 = *(const float4*)(Bp0);
    float4 rb1 = *(const float4*)(Bp1);

    for (int k0 = 0; k0 < DD; k0 += 16) {
        __syncthreads();
        {
            float4 c0 = make_float4(to_tf32(ra0.x), to_tf32(ra0.y), to_tf32(ra0.z), to_tf32(ra0.w));
            float4 c1 = make_float4(to_tf32(ra1.x), to_tf32(ra1.y), to_tf32(ra1.z), to_tf32(ra1.w));
            float4 c2 = make_float4(to_tf32(rb0.x), to_tf32(rb0.y), to_tf32(rb0.z), to_tf32(rb0.w));
            float4 c3 = make_float4(to_tf32(rb1.x), to_tf32(rb1.y), to_tf32(rb1.z), to_tf32(rb1.w));
            *(float4*)&As[a_row0][a_c4*4] = c0;
            *(float4*)&As[a_row1][a_c4*4] = c1;
            *(float4*)&Bs[b_k0][b_n4*4]   = c2;
            *(float4*)&Bs[b_k1][b_n4*4]   = c3;
        }
        __syncthreads();

        if (k0 + 16 < DD) {
            ra0 = *(const float4*)(Ap0 + k0 + 16);
            ra1 = *(const float4*)(Ap1 + k0 + 16);
            rb0 = *(const float4*)(Bp0 + (size_t)(k0 + 16) * DD);
            rb1 = *(const float4*)(Bp1 + (size_t)(k0 + 16) * DD);
        }

#pragma unroll
        for (int kc = 0; kc < 16; kc += 8) {
            uint32_t afr[2][4];
#pragma unroll
            for (int mf = 0; mf < 2; mf++) {
                int m = warpM * 32 + mf * 16;
                afr[mf][0] = __float_as_uint(As[m + gID    ][kc + ct    ]);
                afr[mf][1] = __float_as_uint(As[m + gID + 8][kc + ct    ]);
                afr[mf][2] = __float_as_uint(As[m + gID    ][kc + ct + 4]);
                afr[mf][3] = __float_as_uint(As[m + gID + 8][kc + ct + 4]);
            }
#pragma unroll
            for (int nf = 0; nf < 8; nf++) {
                int n = warpN * 64 + nf * 8 + gID;
                uint32_t bfr[2];
                bfr[0] = __float_as_uint(Bs[kc + ct    ][n]);
                bfr[1] = __float_as_uint(Bs[kc + ct + 4][n]);
                mma_tf32(acc[0][nf], afr[0], bfr);
                mma_tf32(acc[1][nf], afr[1], bfr);
            }
        }
    }

#pragma unroll
    for (int mf = 0; mf < 2; mf++) {
        int r = bm + warpM * 32 + mf * 16 + gID;
#pragma unroll
        for (int nf = 0; nf < 8; nf++) {
            int cidx = bn + warpN * 64 + nf * 8 + ct * 2;
            float b0 = 0.f, b1 = 0.f;
            if (bias) { b0 = bias[cidx]; b1 = bias[cidx + 1]; }
            float2 v0 = make_float2(acc[mf][nf][0] + b0, acc[mf][nf][1] + b1);
            float2 v1 = make_float2(acc[mf][nf][2] + b0, acc[mf][nf][3] + b1);
            if (do_round) {
                v0.x = to_tf32(v0.x); v0.y = to_tf32(v0.y);
                v1.x = to_tf32(v1.x); v1.y = to_tf32(v1.y);
            }
            *(float2*)&C[(size_t)r * DD + cidx] = v0;
            *(float2*)&C[(size_t)(r + 8) * DD + cidx] = v1;
        }
    }
}

// ---------------------------------------------------------------------------
// Flash attention, tf32 MMA, cp.async pipelined, 128q tiles.
// 128 threads = 4 warps, each warp owns 32 q-rows (2 m-frags) and the full
// 64-key range: every K/V B-fragment LDS now feeds TWO MMAs (halved L1
// traffic per unit tensor work vs the 64q version).
// K/V pre-rounded tf32 in gmem -> cp.async ping-pong smem.
// P never touches smem (intra-quad shuffle permute).
// Partial last q-tile (SS=576 = 4*128+64): loads clamp, stores predicated.
// MODE 0 (ress): direct output. MODE 1 (resq): split-KV over blockIdx.z.
// ---------------------------------------------------------------------------
#define KS_STRIDE 68
#define VS_STRIDE 72
#define KS_BUF (64*KS_STRIDE)
#define VS_BUF (64*VS_STRIDE)
#define SMEM_ATTN ((2*KS_BUF + 2*VS_BUF)*4)

template<int MODE>
__global__ __launch_bounds__(128, 2) void attn_mma_kernel(
    const float* __restrict__ Qg, const float* __restrict__ Kg,
    const float* __restrict__ Vg, float* __restrict__ Og,
    float* __restrict__ Opart, float* __restrict__ Ml)
{
    extern __shared__ float sm[];
    float* Ksm = sm;                // [2][64][KS_STRIDE]
    float* Vsm = sm + 2*KS_BUF;     // [2][64][VS_STRIDE]

    const int tid = threadIdx.x;
    const int lid = tid & 31, w = tid >> 5;
    const int gID = lid >> 2, ct = lid & 3;
    const int q0 = blockIdx.x * 128;

    int b, h, f, qf, df = 1, t0, t1;
    if (MODE == 0) {
        int y = blockIdx.y;
        b = y / ((FF-1) * HH);
        int r = y % ((FF-1) * HH);
        f = 1 + r / HH;
        h = r % HH;
        qf = f;
        t0 = 0; t1 = SS / 64;
    } else {
        int y = blockIdx.y;
        b = y >> 3;
        h = y & 7;
        qf = 0; f = 0;
        df = g_df[b];
        int ntot = (SS / 64) * df;
        int sp = blockIdx.z;
        t0 = sp * ntot / NSPLIT;
        t1 = (sp + 1) * ntot / NSPLIT;
    }

    // Row indices for this thread's 4 q-rows (2 m-frags x 2 groups)
    const int rw = q0 + w * 32;
    int qrow[2][2];                 // [mf][grp]
    qrow[0][0] = rw + gID;      qrow[0][1] = rw + gID + 8;
    qrow[1][0] = rw + 16 + gID; qrow[1][1] = rw + 24 + gID;

    // Q fragments (already tf32-rounded in gmem); scale by 1/8 (exact pow2)
    uint32_t qa[2][8][4];
#pragma unroll
    for (int mf = 0; mf < 2; mf++) {
        int r0c = qrow[mf][0] < SS ? qrow[mf][0] : SS-1;
        int r1c = qrow[mf][1] < SS ? qrow[mf][1] : SS-1;
        const size_t base0 = ((size_t)(b*SS + r0c) * FF + qf) * DD + h * CC;
        const size_t base1 = ((size_t)(b*SS + r1c) * FF + qf) * DD + h * CC;
#pragma unroll
        for (int kc = 0; kc < 8; kc++) {
            qa[mf][kc][0] = __float_as_uint(Qg[base0 + kc*8 + ct    ] * 0.125f);
            qa[mf][kc][1] = __float_as_uint(Qg[base1 + kc*8 + ct    ] * 0.125f);
            qa[mf][kc][2] = __float_as_uint(Qg[base0 + kc*8 + ct + 4] * 0.125f);
            qa[mf][kc][3] = __float_as_uint(Qg[base1 + kc*8 + ct + 4] * 0.125f);
        }
    }

    float o[2][8][4];
#pragma unroll
    for (int mf = 0; mf < 2; mf++)
#pragma unroll
        for (int nf = 0; nf < 8; nf++)
#pragma unroll
            for (int r = 0; r < 4; r++) o[mf][nf][r] = 0.f;
    float mrun[2][2], lrun[2][2];
#pragma unroll
    for (int mf = 0; mf < 2; mf++) {
        mrun[mf][0] = -1e30f; mrun[mf][1] = -1e30f;
        lrun[mf][0] = 0.f;    lrun[mf][1] = 0.f;
    }

    // K/V tile load assignment: one key row per pair of threads, 32 c each
    const int key   = tid & 63;
    const int chalf = (tid >> 6) * 32;

    auto row_of = [&](int kt) -> size_t {
        int kg = kt * 64 + key;
        int sk, fk;
        if (MODE == 0) { sk = kg; fk = f; }
        else           { sk = kg / df; fk = g_frames[b][kg - sk*df]; }
        return ((size_t)(b*SS + sk) * FF + fk) * DD + h * CC + chalf;
    };

    auto issue_tile = [&](int kt) {
        size_t r = row_of(kt);
        float* kd = Ksm + (kt & 1) * KS_BUF + key * KS_STRIDE + chalf;
        float* vd = Vsm + (kt & 1) * VS_BUF + key * VS_STRIDE + chalf;
#pragma unroll
        for (int u = 0; u < 8; u++) cp_async16(kd + u*4, Kg + r + u*4);
#pragma unroll
        for (int u = 0; u < 8; u++) cp_async16(vd + u*4, Vg + r + u*4);
    };

    issue_tile(t0);
    CP_COMMIT();

    // Shuffle-permute constants: S D-frag (cols 2t,2t+1) -> PV A-frag (cols t, t+4)
    const int srcA = (lid & ~3) | (ct >> 1);
    const int srcB = srcA + 2;
    const bool hi = (ct & 1);

    for (int kt = t0; kt < t1; kt++) {
        float* Kb = Ksm + (kt & 1) * KS_BUF;
        float* Vb = Vsm + (kt & 1) * VS_BUF;

        if (kt + 1 < t1) {
            issue_tile(kt + 1);
            CP_COMMIT();
            CP_WAIT1();
        } else {
            CP_WAIT0();
        }
        __syncthreads();   // tile kt resident

        // S = (Q*sc) K^T : B-frag loaded once, used by both m-frags
        float s[2][8][4];
#pragma unroll
        for (int mf = 0; mf < 2; mf++)
#pragma unroll
            for (int nf = 0; nf < 8; nf++)
#pragma unroll
                for (int r = 0; r < 4; r++) s[mf][nf][r] = 0.f;
#pragma unroll
        for (int kc = 0; kc < 8; kc++) {
#pragma unroll
            for (int nf = 0; nf < 8; nf++) {
                uint32_t bfr[2];
                bfr[0] = __float_as_uint(Kb[(nf*8 + gID) * KS_STRIDE + kc*8 + ct    ]);
                bfr[1] = __float_as_uint(Kb[(nf*8 + gID) * KS_STRIDE + kc*8 + ct + 4]);
                mma_tf32(s[0][nf], qa[0][kc], bfr);
                mma_tf32(s[1][nf], qa[1][kc], bfr);
            }
        }

        // Online softmax per m-frag (rows gID -> regs 0,1; gID+8 -> regs 2,3)
#pragma unroll
        for (int mf = 0; mf < 2; mf++) {
            float mx0 = -1e30f, mx1 = -1e30f;
#pragma unroll
            for (int nf = 0; nf < 8; nf++) {
                mx0 = fmaxf(mx0, fmaxf(s[mf][nf][0], s[mf][nf][1]));
                mx1 = fmaxf(mx1, fmaxf(s[mf][nf][2], s[mf][nf][3]));
            }
            mx0 = fmaxf(mx0, __shfl_xor_sync(0xffffffffu, mx0, 1));
            mx0 = fmaxf(mx0, __shfl_xor_sync(0xffffffffu, mx0, 2));
            mx1 = fmaxf(mx1, __shfl_xor_sync(0xffffffffu, mx1, 1));
            mx1 = fmaxf(mx1, __shfl_xor_sync(0xffffffffu, mx1, 2));

            float m0n = fmaxf(mrun[mf][0], mx0), m1n = fmaxf(mrun[mf][1], mx1);
            float a0 = __expf(mrun[mf][0] - m0n), a1 = __expf(mrun[mf][1] - m1n);
            float s0 = 0.f, s1 = 0.f;
#pragma unroll
            for (int nf = 0; nf < 8; nf++) {
                s[mf][nf][0] = __expf(s[mf][nf][0] - m0n);
                s[mf][nf][1] = __expf(s[mf][nf][1] - m0n);
                s[mf][nf][2] = __expf(s[mf][nf][2] - m1n);
                s[mf][nf][3] = __expf(s[mf][nf][3] - m1n);
                s0 += s[mf][nf][0] + s[mf][nf][1];
                s1 += s[mf][nf][2] + s[mf][nf][3];
            }
            s0 += __shfl_xor_sync(0xffffffffu, s0, 1);
            s0 += __shfl_xor_sync(0xffffffffu, s0, 2);
            s1 += __shfl_xor_sync(0xffffffffu, s1, 1);
            s1 += __shfl_xor_sync(0xffffffffu, s1, 2);
            lrun[mf][0] = lrun[mf][0] * a0 + s0; mrun[mf][0] = m0n;
            lrun[mf][1] = lrun[mf][1] * a1 + s1; mrun[mf][1] = m1n;
#pragma unroll
            for (int nf = 0; nf < 8; nf++) {
                o[mf][nf][0] *= a0; o[mf][nf][1] *= a0;
                o[mf][nf][2] *= a1; o[mf][nf][3] *= a1;
            }
        }

        // O += P @ V : P A-frags via intra-quad shuffles; V b-frag loaded once,
        // used by both m-frags.
#pragma unroll
        for (int kc2 = 0; kc2 < 8; kc2++) {
            uint32_t pa[2][4];
#pragma unroll
            for (int mf = 0; mf < 2; mf++) {
                float p0 = s[mf][kc2][0], p1 = s[mf][kc2][1];
                float p2 = s[mf][kc2][2], p3 = s[mf][kc2][3];
                float a0v0 = __shfl_sync(0xffffffffu, p0, srcA);
                float a0v1 = __shfl_sync(0xffffffffu, p1, srcA);
                float a1v0 = __shfl_sync(0xffffffffu, p2, srcA);
                float a1v1 = __shfl_sync(0xffffffffu, p3, srcA);
                float a2v0 = __shfl_sync(0xffffffffu, p0, srcB);
                float a2v1 = __shfl_sync(0xffffffffu, p1, srcB);
                float a3v0 = __shfl_sync(0xffffffffu, p2, srcB);
                float a3v1 = __shfl_sync(0xffffffffu, p3, srcB);
                pa[mf][0] = __float_as_uint(to_tf32(hi ? a0v1 : a0v0));
                pa[mf][1] = __float_as_uint(to_tf32(hi ? a1v1 : a1v0));
                pa[mf][2] = __float_as_uint(to_tf32(hi ? a2v1 : a2v0));
                pa[mf][3] = __float_as_uint(to_tf32(hi ? a3v1 : a3v0));
            }
#pragma unroll
            for (int nf = 0; nf < 8; nf++) {
                uint32_t bfr[2];
                bfr[0] = __float_as_uint(Vb[(kc2*8 + ct    ) * VS_STRIDE + nf*8 + gID]);
                bfr[1] = __float_as_uint(Vb[(kc2*8 + ct + 4) * VS_STRIDE + nf*8 + gID]);
                mma_tf32(o[0][nf], pa[0], bfr);
                mma_tf32(o[1][nf], pa[1], bfr);
            }
        }

        __syncthreads();   // everyone done with tile kt before next overwrite
    }

    // Epilogue (predicated on valid rows; only last q-tile has invalid ones)
#pragma unroll
    for (int mf = 0; mf < 2; mf++) {
        const float inv0 = 1.0f / lrun[mf][0], inv1 = 1.0f / lrun[mf][1];
        const int r0 = qrow[mf][0], r1 = qrow[mf][1];
        const bool v0 = (r0 < SS), v1 = (r1 < SS);
        if (MODE == 0) {
            const size_t ob0 = ((size_t)(b*SS + (v0 ? r0 : 0)) * FF + f) * DD + h * CC;
            const size_t ob1 = ((size_t)(b*SS + (v1 ? r1 : 0)) * FF + f) * DD + h * CC;
#pragma unroll
            for (int nf = 0; nf < 8; nf++) {
                int col = nf * 8 + ct * 2;
                if (v0) *(float2*)&Og[ob0 + col] =
                    make_float2(o[mf][nf][0] * inv0, o[mf][nf][1] * inv0);
                if (v1) *(float2*)&Og[ob1 + col] =
                    make_float2(o[mf][nf][2] * inv1, o[mf][nf][3] * inv1);
            }
        } else {
            const int y = blockIdx.y, sp = blockIdx.z;
            const size_t pb0 = ((size_t)(sp*(BB*HH) + y) * SS + (v0 ? r0 : 0)) * CC;
            const size_t pb1 = ((size_t)(sp*(BB*HH) + y) * SS + (v1 ? r1 : 0)) * CC;
#pragma unroll
            for (int nf = 0; nf < 8; nf++) {
                int col = nf * 8 + ct * 2;
                if (v0) *(float2*)&Opart[pb0 + col] =
                    make_float2(o[mf][nf][0] * inv0, o[mf][nf][1] * inv0);
                if (v1) *(float2*)&Opart[pb1 + col] =
                    make_float2(o[mf][nf][2] * inv1, o[mf][nf][3] * inv1);
            }
            if (ct == 0) {
                const int y2 = blockIdx.y, sp2 = blockIdx.z;
                if (v0) {
                    size_t mb0 = ((size_t)(sp2*(BB*HH) + y2) * SS + r0) * 2;
                    Ml[mb0 + 0] = mrun[mf][0]; Ml[mb0 + 1] = lrun[mf][0];
                }
                if (v1) {
                    size_t mb1 = ((size_t)(sp2*(BB*HH) + y2) * SS + r1) * 2;
                    Ml[mb1 + 0] = mrun[mf][1]; Ml[mb1 + 1] = lrun[mf][1];
                }
            }
        }
    }
}

// ---------------------------------------------------------------------------
// Merge resq split partials into g_att frame 0.
// ---------------------------------------------------------------------------
__global__ __launch_bounds__(256) void merge_resq_kernel(float* __restrict__ att)
{
    int idx = blockIdx.x * 256 + threadIdx.x;           // over 16*576*16
    if (idx >= BB*HH*SS*(CC/4)) return;
    int c4 = idx & 15;
    int q  = (idx >> 4) % SS;
    int y  = idx / (16 * SS);

    float m[NSPLIT], l[NSPLIT];
    float mmax = -1e30f;
#pragma unroll
    for (int s = 0; s < NSPLIT; s++) {
        size_t mb = ((size_t)(s*(BB*HH) + y) * SS + q) * 2;
        m[s] = g_ml[mb]; l[s] = g_ml[mb + 1];
        mmax = fmaxf(mmax, m[s]);
    }
    float4 acc = make_float4(0.f, 0.f, 0.f, 0.f);
    float wsum = 0.f;
#pragma unroll
    for (int s = 0; s < NSPLIT; s++) {
        float wgt = __expf(m[s] - mmax) * l[s];
        const float4 ov = *(const float4*)&g_opart[(((size_t)(s*(BB*HH) + y) * SS + q) * CC) + c4*4];
        acc.x += wgt * ov.x; acc.y += wgt * ov.y;
        acc.z += wgt * ov.z; acc.w += wgt * ov.w;
        wsum += wgt;
    }
    float inv = 1.0f / wsum;
    int b = y >> 3, h = y & 7;
    float4 r = make_float4(acc.x*inv, acc.y*inv, acc.z*inv, acc.w*inv);
    *(float4*)&att[((size_t)(b*SS + q) * FF + 0) * DD + h*CC + c4*4] = r;
}

// ---------------------------------------------------------------------------
extern "C" void kernel_launch(void* const* d_in, const int* in_sizes, int n_in,
                              void* d_out, int out_size)
{
    const float* x    = (const float*)d_in[0];
    const int*   mask = (const int*)  d_in[1];
    const float* Wq   = (const float*)d_in[2];
    const float* Wk   = (const float*)d_in[3];
    const float* Wv   = (const float*)d_in[4];
    const float* Wout = (const float*)d_in[5];
    const float* bout = (const float*)d_in[6];
    float* out = (float*)d_out;

    float *q, *k, *v, *att, *opart, *ml;
    cudaGetSymbolAddress((void**)&q,     g_q);
    cudaGetSymbolAddress((void**)&k,     g_k);
    cudaGetSymbolAddress((void**)&v,     g_v);
    cudaGetSymbolAddress((void**)&att,   g_att);
    cudaGetSymbolAddress((void**)&opart, g_opart);
    cudaGetSymbolAddress((void**)&ml,    g_ml);

    static bool attr_set = false;
    if (!attr_set) {
        cudaFuncSetAttribute(attn_mma_kernel<0>,
            cudaFuncAttributeMaxDynamicSharedMemorySize, SMEM_ATTN);
        cudaFuncSetAttribute(attn_mma_kernel<1>,
            cudaFuncAttributeMaxDynamicSharedMemorySize, SMEM_ATTN);
        attr_set = true;
    }

    build_frames_kernel<<<1, 32>>>(mask);

    // Fused QKV projections; outputs pre-rounded to tf32 for the attention
    gemm_tf32_kernel<<<dim3(MROWS/128, DD/128, 3), 256>>>(
        x, Wq, Wk, Wv, q, k, v, nullptr, 1);

    const int QTILES = (SS + 127) / 128;   // 5 (last tile partial)
    // ress: per-frame self attention, frames 1..15
    attn_mma_kernel<0><<<dim3(QTILES, BB*(FF-1)*HH, 1), 128, SMEM_ATTN>>>(
        q, k, v, att, nullptr, nullptr);
    // resq: split-KV over NSPLIT
    attn_mma_kernel<1><<<dim3(QTILES, BB*HH, NSPLIT), 128, SMEM_ATTN>>>(
        q, k, v, att, opart, ml);
    merge_resq_kernel<<<(BB*HH*SS*(CC/4) + 255)/256, 256>>>(att);

    // Output projection + bias (final output: NOT rounded)
    gemm_tf32_kernel<<<dim3(MROWS/128, DD/128, 1), 256>>>(
        att, Wout, Wout, Wout, out, out, out, bout, 0);
}